// round 5
// baseline (speedup 1.0000x reference)
#include <cuda_runtime.h>
#include <math.h>

// ---------------------------------------------------------------------------
// YOLOv3 loss, B=32. Layers: 13x13 / 26x26 / 52x52, 3 anchors, 80 classes.
// y_true: (32, 3549, 3, 85) fp32 ; preds: (32,H,W,255) fp32 ; out: (32,) fp32
//
// Two kernels:
//   k_prep <<<96,256>>> : per (b,layer) block — obj bitmask (ballot), ordered
//                         compaction of positive boxes (exact top-64), positive
//                         xy/wh/cls loss -> g_posloss[bl]. Overwrites all state
//                         (no init kernel). Block 0 zeroes out.
//   k_main <<<352,256>>>: per (b,layer,chunk of 1024 anchors), 4 anchors/thread,
//                         conf-BCE + IoU-ignore vs box list; one atomic/block.
// ---------------------------------------------------------------------------

#define NB    32
#define NBL   96
#define PMAX  128    // positive-list capacity (expected max ~30)

__device__ int      g_fcnt[NBL];            // box-list count (<=64)
__device__ float4   g_fA[NBL][64];          // (minx,miny,maxx,maxy)
__device__ float    g_fArea[NBL][64];
__device__ float    g_posloss[NBL];
__device__ unsigned g_mask[NBL * 256];      // per-segment obj bitmask

__constant__ float c_anc[9][2] = {
    {116.f, 90.f}, {156.f, 198.f}, {373.f, 326.f},
    { 30.f, 61.f}, { 62.f,  45.f}, { 59.f, 119.f},
    { 10.f, 13.f}, { 16.f,  30.f}, { 33.f,  23.f}};

__device__ __forceinline__ float sigf(float x) {
    return __fdividef(1.f, 1.f + __expf(-x));
}
// bce_logits(t, x) for x in (0,1): max(x,0)=x, |x|=x
__device__ __forceinline__ float bce01(float t, float x) {
    return x - x * t + __logf(1.f + __expf(-x));
}

// ============================ k_prep =========================================
template<int SEGLEN, int NT, int W, int LAYER, int CELLOFF>
__device__ void prep_seg(int b, int bl, const float* __restrict__ yt,
                         const float* __restrict__ pred) {
    __shared__ int   s_wcnt[8];
    __shared__ int   s_loc[PMAX];
    __shared__ float s_red[8];
    const unsigned FULL = 0xffffffffu;
    int tid = threadIdx.x, wid = tid >> 5, lane = tid & 31;

    const float* segbase = yt + ((size_t)b * 3549 + CELLOFF) * 3 * 85;

    // --- prefetch obj predicates for all tiles (independent loads, full MLP)
    unsigned posbits = 0;
    #pragma unroll
    for (int t = 0; t < NT; t++) {
        int loc = t * 256 + tid;
        if (loc < SEGLEN) {
            if (__ldg(segbase + (size_t)loc * 85) > 0.5f) posbits |= (1u << t);
        }
    }

    // --- per-tile: mask word + ordered compaction of positives
    int total = 0;
    #pragma unroll
    for (int t = 0; t < NT; t++) {
        bool pos = (posbits >> t) & 1u;
        unsigned m = __ballot_sync(FULL, pos);
        if (lane == 0) {
            g_mask[bl * 256 + t * 8 + wid] = m;
            s_wcnt[wid] = __popc(m);
        }
        __syncthreads();
        int wbase = 0, ttot = 0;
        #pragma unroll
        for (int i = 0; i < 8; i++) {
            int c = s_wcnt[i];
            wbase += (i < wid) ? c : 0;
            ttot  += c;
        }
        if (pos) {
            int loc  = t * 256 + tid;
            int slot = total + wbase + __popc(m & ((1u << lane) - 1u));
            if (slot < PMAX) s_loc[slot] = loc;
            if (slot < 64) {
                const float* tb = segbase + (size_t)loc * 85;
                float t1 = __ldg(tb + 1), t2 = __ldg(tb + 2);
                float t3 = __ldg(tb + 3), t4 = __ldg(tb + 4);
                g_fA[bl][slot] = make_float4(t1 - 0.5f * t3, t2 - 0.5f * t4,
                                             t1 + 0.5f * t3, t2 + 0.5f * t4);
                g_fArea[bl][slot] = t3 * t4;
            }
        }
        total += ttot;
        __syncthreads();
    }
    if (tid == 0) g_fcnt[bl] = min(total, 64);

    // --- positive-anchor loss (warp per positive)
    int pcnt = min(total, PMAX);
    float acc = 0.f;
    constexpr float fW = (float)W;
    constexpr float invW = 1.f / (float)W;
    for (int k = wid; k < pcnt; k += 8) {
        int loc = s_loc[k];
        int cell = loc / 3, a = loc - cell * 3;
        int hh = cell / W, ww = cell - hh * W;
        const float* tb = segbase + (size_t)loc * 85;
        const float* pb = pred + ((size_t)(b * (W * W) + cell)) * 255 + a * 85;
        float aw = c_anc[3 * LAYER + a][0];
        float ah = c_anc[3 * LAYER + a][1];

        // group 0: channels 1..32
        float t0 = __ldg(tb + lane + 1), q0 = __ldg(pb + lane + 1);
        float tw = __shfl_sync(FULL, t0, 2);   // yt ch3
        float th = __shfl_sync(FULL, t0, 3);   // yt ch4
        float scale = 2.f - tw * th;
        float l = 0.f;
        if (lane == 0) {          // x
            float x = (sigf(q0) + (float)ww) * invW;
            float t = t0 * fW - (float)ww;
            l = scale * bce01(t, x);
        } else if (lane == 1) {   // y
            float x = (sigf(q0) + (float)hh) * invW;
            float t = t0 * fW - (float)hh;
            l = scale * bce01(t, x);
        } else if (lane == 2) {   // w
            float wp = __expf(q0) * aw * invW;
            float t = __logf(t0 * (416.f / aw));
            float d = t - wp;
            l = scale * 0.5f * d * d;
        } else if (lane == 3) {   // h
            float hp = __expf(q0) * ah * invW;
            float t = __logf(t0 * (416.f / ah));
            float d = t - hp;
            l = scale * 0.5f * d * d;
        } else {                  // cls channels 5..32
            l = bce01(t0, sigf(q0));
        }
        // group 1: channels 33..64 (cls)
        float t1 = __ldg(tb + lane + 33), q1 = __ldg(pb + lane + 33);
        l += bce01(t1, sigf(q1));
        // group 2: channels 65..84 (cls)
        if (lane < 20) {
            float t2 = __ldg(tb + lane + 65), q2 = __ldg(pb + lane + 65);
            l += bce01(t2, sigf(q2));
        }
        acc += l;
    }
    #pragma unroll
    for (int o = 16; o; o >>= 1) acc += __shfl_xor_sync(FULL, acc, o);
    if (lane == 0) s_red[wid] = acc;
    __syncthreads();
    if (tid == 0) {
        float v = 0.f;
        #pragma unroll
        for (int i = 0; i < 8; i++) v += s_red[i];
        g_posloss[bl] = v;
    }
}

__global__ __launch_bounds__(256)
void k_prep(const float* __restrict__ yt,
            const float* __restrict__ p13,
            const float* __restrict__ p26,
            const float* __restrict__ p52,
            float* __restrict__ out) {
    int bl = blockIdx.x;
    if (bl == 0 && threadIdx.x < NB) out[threadIdx.x] = 0.f;
    int b = bl / 3, layer = bl - b * 3;
    if (layer == 0)      prep_seg< 507,  2, 13, 0, 0>  (b, bl, yt, p13);
    else if (layer == 1) prep_seg<2028,  8, 26, 1, 169>(b, bl, yt, p26);
    else                 prep_seg<8112, 32, 52, 2, 845>(b, bl, yt, p52);
}

// ============================ k_main =========================================
template<int SEGLEN, int W, int LAYER>
__device__ float main_seg(int b, int bl, int chunk,
                          const float* __restrict__ pred, int cnt) {
    float pminx[4], pminy[4], pmaxx[4], pmaxy[4], pa[4], cb[4];
    bool valid[4], objb[4], hit[4];
    constexpr float invW = 1.f / (float)W;

    #pragma unroll
    for (int j = 0; j < 4; j++) {
        int loc = chunk * 1024 + j * 256 + threadIdx.x;
        valid[j] = (loc < SEGLEN);
        hit[j] = false;
        if (valid[j]) {
            int cell = loc / 3, a = loc - cell * 3;
            int hh = cell / W, ww = cell - hh * W;
            const float* pb = pred + ((size_t)(b * (W * W) + cell)) * 255 + a * 85;

            unsigned mw = g_mask[bl * 256 + (loc >> 5)];
            objb[j] = (mw >> (loc & 31)) & 1u;

            float q0 = __ldg(pb);
            float q1 = __ldg(pb + 1), q2 = __ldg(pb + 2);
            float q3 = __ldg(pb + 3), q4 = __ldg(pb + 4);

            float aw = c_anc[3 * LAYER + a][0];
            float ah = c_anc[3 * LAYER + a][1];
            float bx = (sigf(q1) + (float)ww) * invW;
            float by = (sigf(q2) + (float)hh) * invW;
            float bw = __expf(q3) * (aw * invW);
            float bh = __expf(q4) * (ah * invW);
            float hx = 0.5f * bw, hy = 0.5f * bh;
            pminx[j] = bx - hx; pmaxx[j] = bx + hx;
            pminy[j] = by - hy; pmaxy[j] = by + hy;
            pa[j] = bw * bh;
            cb[j] = bce01(objb[j] ? 1.f : 0.f, sigf(q0));
        } else {
            objb[j] = false; cb[j] = 0.f;
            pminx[j] = pmaxx[j] = pminy[j] = pmaxy[j] = pa[j] = 0.f;
        }
    }

    for (int k = 0; k < cnt; k++) {
        float4 A = __ldg(&g_fA[bl][k]);
        float ta = __ldg(&g_fArea[bl][k]);
        #pragma unroll
        for (int j = 0; j < 4; j++) {
            float iw = fminf(pmaxx[j], A.z) - fmaxf(pminx[j], A.x);
            float ih = fminf(pmaxy[j], A.w) - fmaxf(pminy[j], A.y);
            iw = fmaxf(iw, 0.f); ih = fmaxf(ih, 0.f);
            float inter = iw * ih;
            hit[j] = hit[j] || (3.f * inter >= pa[j] + ta);  // iou >= 0.5
        }
    }

    float lsum = 0.f;
    #pragma unroll
    for (int j = 0; j < 4; j++) {
        if (valid[j])
            lsum += cb[j] * (objb[j] ? 1.f : (hit[j] ? 0.f : 1.f));
    }
    return lsum;
}

__global__ __launch_bounds__(256)
void k_main(const float* __restrict__ p13,
            const float* __restrict__ p26,
            const float* __restrict__ p52,
            float* __restrict__ out) {
    __shared__ float s_red[8];
    const unsigned FULL = 0xffffffffu;

    int blk = blockIdx.x;
    int b = blk / 11, r = blk - b * 11;

    float lsum;
    int bl;
    if (r == 0) {
        bl = b * 3;
        lsum = main_seg< 507, 13, 0>(b, bl, 0, p13, g_fcnt[bl]);
    } else if (r < 3) {
        bl = b * 3 + 1;
        lsum = main_seg<2028, 26, 1>(b, bl, r - 1, p26, g_fcnt[bl]);
    } else {
        bl = b * 3 + 2;
        lsum = main_seg<8112, 52, 2>(b, bl, r - 3, p52, g_fcnt[bl]);
    }

    #pragma unroll
    for (int o = 16; o; o >>= 1) lsum += __shfl_xor_sync(FULL, lsum, o);
    int wid = threadIdx.x >> 5, lane = threadIdx.x & 31;
    if (lane == 0) s_red[wid] = lsum;
    __syncthreads();
    if (threadIdx.x == 0) {
        float v = 0.f;
        #pragma unroll
        for (int i = 0; i < 8; i++) v += s_red[i];
        if (r == 0)   // fold in the positive-term loss once per batch
            v += g_posloss[3 * b] + g_posloss[3 * b + 1] + g_posloss[3 * b + 2];
        atomicAdd(out + b, v);
    }
}

// ---------------------------------------------------------------------------
extern "C" void kernel_launch(void* const* d_in, const int* in_sizes, int n_in,
                              void* d_out, int out_size) {
    const float* yt  = (const float*)d_in[0];
    const float* p13 = (const float*)d_in[1];
    const float* p26 = (const float*)d_in[2];
    const float* p52 = (const float*)d_in[3];
    float* out = (float*)d_out;

    k_prep<<<NBL, 256>>>(yt, p13, p26, p52, out);
    k_main<<<NB * 11, 256>>>(p13, p26, p52, out);
}

// round 6
// speedup vs baseline: 2.0791x; 2.0791x over previous
#include <cuda_runtime.h>
#include <math.h>

// ---------------------------------------------------------------------------
// YOLOv3 loss, B=32. Layers: 13x13 / 26x26 / 52x52, 3 anchors, 80 classes.
// y_true: (32, 3549, 3, 85) fp32 ; preds: (32,H,W,255) fp32 ; out: (32,) fp32
//
// Two kernels, no init, no atomic staging:
//  k_mask <<<672,256>>> : per (b,layer,chunk-of-512): obj bitmask via ballot
//                         into per-segment-aligned words. Block 0 zeroes out.
//  k_main <<<768,256>>> : blocks [0,96)   -> positive xy/wh/cls loss
//                         blocks [96,768) -> conf-BCE + IoU-ignore, 2 anch/thr.
//                         Every block rebuilds its (b,layer) box list from the
//                         mask via a block prefix scan (exact ordered top-64).
// ---------------------------------------------------------------------------

#define NB    32
#define NBL   96
#define PMAX  128
#define FULLM 0xffffffffu

__device__ unsigned g_mask[NBL * 256];   // word w of segment bl = anchors [32w,32w+32)

__constant__ float c_anc[9][2] = {
    {116.f, 90.f}, {156.f, 198.f}, {373.f, 326.f},
    { 30.f, 61.f}, { 62.f,  45.f}, { 59.f, 119.f},
    { 10.f, 13.f}, { 16.f,  30.f}, { 33.f,  23.f}};

__device__ __forceinline__ float sigf(float x) {
    return __fdividef(1.f, 1.f + __expf(-x));
}
// bce_logits(t, x) for x in (0,1): max(x,0)=x, |x|=x
__device__ __forceinline__ float bce01(float t, float x) {
    return x - x * t + __logf(1.f + __expf(-x));
}

// r in [0,21) -> (layer, chunk): 0 -> L0/c0 ; 1..4 -> L1/c(r-1) ; 5..20 -> L2/c(r-5)
__device__ __forceinline__ void rmap(int r, int& layer, int& chunk) {
    if (r == 0)      { layer = 0; chunk = 0; }
    else if (r < 5)  { layer = 1; chunk = r - 1; }
    else             { layer = 2; chunk = r - 5; }
}

// ============================ k_mask =========================================
__global__ __launch_bounds__(256)
void k_mask(const float* __restrict__ yt, float* __restrict__ out) {
    int blk = blockIdx.x;
    if (blk == 0 && threadIdx.x < NB) out[threadIdx.x] = 0.f;

    int b = blk / 21, r = blk - b * 21;
    int layer, chunk;
    rmap(r, layer, chunk);
    int seglen  = (layer == 0) ? 507 : (layer == 1) ? 2028 : 8112;
    int celloff = (layer == 0) ? 0   : (layer == 1) ? 169  : 845;
    int bl = b * 3 + layer;
    const float* segbase = yt + ((size_t)b * 3549 + celloff) * 255;

    int lane = threadIdx.x & 31;
    int loc0 = chunk * 512 + threadIdx.x;
    int loc1 = loc0 + 256;
    bool p0 = (loc0 < seglen) && (__ldg(segbase + (size_t)loc0 * 85) > 0.5f);
    bool p1 = (loc1 < seglen) && (__ldg(segbase + (size_t)loc1 * 85) > 0.5f);
    unsigned m0 = __ballot_sync(FULLM, p0);
    unsigned m1 = __ballot_sync(FULLM, p1);
    if (lane == 0) {
        g_mask[bl * 256 + (loc0 >> 5)] = m0;
        g_mask[bl * 256 + (loc1 >> 5)] = m1;
    }
}

// ============================ box-list rebuild ===============================
// Ordered compaction of set mask bits (ascending anchor index == exact stable
// top-k membership). Boxes (min/max/area) to smem for slots < 64; optional loc
// list (slots < PMAX) for the positive-loss path. Returns total positives.
__device__ int build_list(int bl, int nword, const float* __restrict__ segbase,
                          float4* sA, float* sArea, int* s_loc, int* s_wtot) {
    int tid = threadIdx.x, wid = tid >> 5, lane = tid & 31;
    unsigned w = (tid < nword) ? g_mask[bl * 256 + tid] : 0u;
    int c = __popc(w);

    // inclusive warp scan of c
    int sc = c;
    #pragma unroll
    for (int o = 1; o < 32; o <<= 1) {
        int v = __shfl_up_sync(FULLM, sc, o);
        if (lane >= o) sc += v;
    }
    if (lane == 31) s_wtot[wid] = sc;
    __syncthreads();
    int wbase = 0, total = 0;
    #pragma unroll
    for (int i = 0; i < 8; i++) {
        int t = s_wtot[i];
        wbase += (i < wid) ? t : 0;
        total += t;
    }
    int slot = wbase + sc - c;     // exclusive prefix for this thread's word

    unsigned ww = w;
    while (ww) {
        int bit = __ffs(ww) - 1;
        ww &= ww - 1;
        int loc = tid * 32 + bit;
        if (s_loc && slot < PMAX) s_loc[slot] = loc;
        if (slot < 64) {
            const float* tb = segbase + (size_t)loc * 85;
            float t1 = __ldg(tb + 1), t2 = __ldg(tb + 2);
            float t3 = __ldg(tb + 3), t4 = __ldg(tb + 4);
            sA[slot] = make_float4(t1 - 0.5f * t3, t2 - 0.5f * t4,
                                   t1 + 0.5f * t3, t2 + 0.5f * t4);
            sArea[slot] = t3 * t4;
        }
        slot++;
    }
    __syncthreads();
    return total;
}

// ============================ conf path ======================================
template<int W, int LAYER, int CELLOFF, int NWORD>
__device__ float conf_work(int b, int bl, int chunk,
                           const float* __restrict__ yt,
                           const float* __restrict__ pred,
                           float4* sA, float* sArea, int* s_wtot) {
    constexpr int SEGLEN = W * W * 3;
    constexpr float invW = 1.f / (float)W;
    const float* segbase = yt + ((size_t)b * 3549 + CELLOFF) * 255;
    int total = build_list(bl, NWORD, segbase, sA, sArea, nullptr, s_wtot);
    int cnt = min(total, 64);

    const float* pbase = pred + (size_t)b * (W * W * 255);

    float pminx[2], pminy[2], pmaxx[2], pmaxy[2], pa[2], cb[2];
    bool valid[2], objb[2], hit[2];
    #pragma unroll
    for (int j = 0; j < 2; j++) {
        int loc = chunk * 512 + j * 256 + threadIdx.x;
        valid[j] = (loc < SEGLEN);
        hit[j] = false;
        objb[j] = false; cb[j] = 0.f;
        pminx[j] = pmaxx[j] = pminy[j] = pmaxy[j] = pa[j] = 0.f;
        if (valid[j]) {
            int cell = loc / 3, a = loc - cell * 3;
            int hh = cell / W, ww = cell - hh * W;
            const float* pb = pbase + (size_t)loc * 85;
            unsigned mw = g_mask[bl * 256 + (loc >> 5)];
            objb[j] = (mw >> (loc & 31)) & 1u;

            float q0 = __ldg(pb);
            float q1 = __ldg(pb + 1), q2 = __ldg(pb + 2);
            float q3 = __ldg(pb + 3), q4 = __ldg(pb + 4);
            float aw = c_anc[3 * LAYER + a][0];
            float ah = c_anc[3 * LAYER + a][1];
            float bx = (sigf(q1) + (float)ww) * invW;
            float by = (sigf(q2) + (float)hh) * invW;
            float bw = __expf(q3) * (aw * invW);
            float bh = __expf(q4) * (ah * invW);
            float hx = 0.5f * bw, hy = 0.5f * bh;
            pminx[j] = bx - hx; pmaxx[j] = bx + hx;
            pminy[j] = by - hy; pmaxy[j] = by + hy;
            pa[j] = bw * bh;
            cb[j] = bce01(objb[j] ? 1.f : 0.f, sigf(q0));
        }
    }

    for (int k = 0; k < cnt; k++) {
        float4 A = sA[k];
        float ta = sArea[k];
        #pragma unroll
        for (int j = 0; j < 2; j++) {
            float iw = fminf(pmaxx[j], A.z) - fmaxf(pminx[j], A.x);
            float ih = fminf(pmaxy[j], A.w) - fmaxf(pminy[j], A.y);
            float inter = fmaxf(iw, 0.f) * fmaxf(ih, 0.f);
            hit[j] = hit[j] || (3.f * inter >= pa[j] + ta);   // iou >= 0.5
        }
    }

    float lsum = 0.f;
    #pragma unroll
    for (int j = 0; j < 2; j++)
        if (valid[j]) lsum += cb[j] * (objb[j] ? 1.f : (hit[j] ? 0.f : 1.f));
    return lsum;
}

// ============================ positive path ==================================
template<int W, int LAYER, int CELLOFF, int NWORD>
__device__ void pos_work(int b, int bl,
                         const float* __restrict__ yt,
                         const float* __restrict__ pred,
                         float* __restrict__ out,
                         float4* sA, float* sArea, int* s_loc, int* s_wtot,
                         float* s_red) {
    constexpr float fW = (float)W;
    constexpr float invW = 1.f / (float)W;
    const float* segbase = yt + ((size_t)b * 3549 + CELLOFF) * 255;
    int total = build_list(bl, NWORD, segbase, sA, sArea, s_loc, s_wtot);
    int pcnt = min(total, PMAX);
    if (pcnt == 0) return;

    const float* pbase = pred + (size_t)b * (W * W * 255);
    int wid = threadIdx.x >> 5, lane = threadIdx.x & 31;

    float acc = 0.f;
    for (int k = wid; k < pcnt; k += 8) {
        int loc = s_loc[k];
        int cell = loc / 3, a = loc - cell * 3;
        int hh = cell / W, ww = cell - hh * W;
        const float* tb = segbase + (size_t)loc * 85;
        const float* pb = pbase + (size_t)loc * 85;
        float aw = c_anc[3 * LAYER + a][0];
        float ah = c_anc[3 * LAYER + a][1];

        // group 0: channels 1..32
        float t0 = __ldg(tb + lane + 1), q0 = __ldg(pb + lane + 1);
        float tw = __shfl_sync(FULLM, t0, 2);    // yt ch3
        float th = __shfl_sync(FULLM, t0, 3);    // yt ch4
        float scale = 2.f - tw * th;
        float l = 0.f;
        if (lane == 0) {          // x
            float x = (sigf(q0) + (float)ww) * invW;
            float t = t0 * fW - (float)ww;
            l = scale * bce01(t, x);
        } else if (lane == 1) {   // y
            float x = (sigf(q0) + (float)hh) * invW;
            float t = t0 * fW - (float)hh;
            l = scale * bce01(t, x);
        } else if (lane == 2) {   // w
            float wp = __expf(q0) * aw * invW;
            float t = __logf(t0 * (416.f / aw));
            float d = t - wp;
            l = scale * 0.5f * d * d;
        } else if (lane == 3) {   // h
            float hp = __expf(q0) * ah * invW;
            float t = __logf(t0 * (416.f / ah));
            float d = t - hp;
            l = scale * 0.5f * d * d;
        } else {                  // cls channels 5..32
            l = bce01(t0, sigf(q0));
        }
        // group 1: channels 33..64 (cls)
        float t1 = __ldg(tb + lane + 33), q1 = __ldg(pb + lane + 33);
        l += bce01(t1, sigf(q1));
        // group 2: channels 65..84 (cls)
        if (lane < 20) {
            float t2 = __ldg(tb + lane + 65), q2 = __ldg(pb + lane + 65);
            l += bce01(t2, sigf(q2));
        }
        acc += l;
    }
    #pragma unroll
    for (int o = 16; o; o >>= 1) acc += __shfl_xor_sync(FULLM, acc, o);
    if (lane == 0) s_red[wid] = acc;
    __syncthreads();
    if (threadIdx.x == 0) {
        float v = 0.f;
        #pragma unroll
        for (int i = 0; i < 8; i++) v += s_red[i];
        if (v != 0.f) atomicAdd(out + b, v);
    }
}

// ============================ k_main =========================================
__global__ __launch_bounds__(256, 5)
void k_main(const float* __restrict__ yt,
            const float* __restrict__ p13,
            const float* __restrict__ p26,
            const float* __restrict__ p52,
            float* __restrict__ out) {
    __shared__ float4 sA[64];
    __shared__ float  sArea[64];
    __shared__ int    s_loc[PMAX];
    __shared__ int    s_wtot[8];
    __shared__ float  s_red[8];

    int blk = blockIdx.x;
    if (blk < NBL) {
        int b = blk / 3, layer = blk - b * 3;
        if (layer == 0)
            pos_work<13, 0, 0, 16>  (b, blk, yt, p13, out, sA, sArea, s_loc, s_wtot, s_red);
        else if (layer == 1)
            pos_work<26, 1, 169, 64>(b, blk, yt, p26, out, sA, sArea, s_loc, s_wtot, s_red);
        else
            pos_work<52, 2, 845, 254>(b, blk, yt, p52, out, sA, sArea, s_loc, s_wtot, s_red);
        return;
    }

    blk -= NBL;
    int b = blk / 21, r = blk - b * 21;
    int layer, chunk;
    rmap(r, layer, chunk);
    int bl = b * 3 + layer;

    float lsum;
    if (layer == 0)
        lsum = conf_work<13, 0, 0, 16>  (b, bl, chunk, yt, p13, sA, sArea, s_wtot);
    else if (layer == 1)
        lsum = conf_work<26, 1, 169, 64>(b, bl, chunk, yt, p26, sA, sArea, s_wtot);
    else
        lsum = conf_work<52, 2, 845, 254>(b, bl, chunk, yt, p52, sA, sArea, s_wtot);

    #pragma unroll
    for (int o = 16; o; o >>= 1) lsum += __shfl_xor_sync(FULLM, lsum, o);
    int wid = threadIdx.x >> 5, lane = threadIdx.x & 31;
    if (lane == 0) s_red[wid] = lsum;
    __syncthreads();
    if (threadIdx.x == 0) {
        float v = 0.f;
        #pragma unroll
        for (int i = 0; i < 8; i++) v += s_red[i];
        atomicAdd(out + b, v);
    }
}

// ---------------------------------------------------------------------------
extern "C" void kernel_launch(void* const* d_in, const int* in_sizes, int n_in,
                              void* d_out, int out_size) {
    const float* yt  = (const float*)d_in[0];
    const float* p13 = (const float*)d_in[1];
    const float* p26 = (const float*)d_in[2];
    const float* p52 = (const float*)d_in[3];
    float* out = (float*)d_out;

    k_mask<<<NB * 21, 256>>>(yt, out);
    k_main<<<NBL + NB * 21, 256>>>(yt, p13, p26, p52, out);
}